// round 15
// baseline (speedup 1.0000x reference)
#include <cuda_runtime.h>
#include <cstdint>

#define BB   8
#define CC   512
#define TT   1024
#define NHH  8
#define CHH  64
#define NG   32
#define CPG  16

#if (defined(__CUDA_ARCH_FEAT_SM103_ALL) || defined(__CUDA_ARCH_FEAT_SM100_ALL) || defined(__CUDA_ARCH_FEAT_SM110_ALL))
#define HAS_TCGEN05 1
#else
#define HAS_TCGEN05 0
#endif

__device__ float g_qkv[BB * 3 * CC * TT];
__device__ float g_a[BB * CC * TT];
__device__ float g_scale[BB * CC];
__device__ float g_shift[BB * CC];

__device__ __forceinline__ uint32_t smem_u32(const void* p) {
    uint32_t a;
    asm("{ .reg .u64 t; cvta.to.shared.u64 t, %1; cvt.u32.u64 %0, t; }" : "=r"(a) : "l"(p));
    return a;
}
#if HAS_TCGEN05
__device__ __forceinline__ uint32_t elect_one() {
    uint32_t pred;
    asm volatile("{\n\t.reg .pred p;\n\telect.sync _|p, 0xFFFFFFFF;\n\t"
                 "selp.b32 %0, 1, 0, p;\n\t}" : "=r"(pred));
    return pred;
}
#define TC_ALLOC(smem_addr, n) \
    asm volatile("tcgen05.alloc.cta_group::1.sync.aligned.shared::cta.b32 [%0], %1;" \
                 :: "r"((uint32_t)(smem_addr)), "r"((uint32_t)(n)) : "memory")
#define TC_DEALLOC(tmem, n) \
    asm volatile("tcgen05.dealloc.cta_group::1.sync.aligned.b32 %0, %1;" :: "r"(tmem), "r"((uint32_t)(n)))
#define TC_RELINQ() asm volatile("tcgen05.relinquish_alloc_permit.cta_group::1.sync.aligned;")
#define TC_COMMIT(mbar) \
    asm volatile("tcgen05.commit.cta_group::1.mbarrier::arrive::one.shared::cluster.b64 [%0];" \
                 :: "r"((uint32_t)(mbar)) : "memory")
#define TC_FENCE_BEFORE() asm volatile("tcgen05.fence::before_thread_sync;" ::: "memory")
#define TC_FENCE_AFTER()  asm volatile("tcgen05.fence::after_thread_sync;" ::: "memory")
#define TC_WAIT_LD() asm volatile("tcgen05.wait::ld.sync.aligned;" ::: "memory")
#define TC_WAIT_ST() asm volatile("tcgen05.wait::st.sync.aligned;" ::: "memory")
#define MBAR_INIT(mbar, cnt) \
    asm volatile("mbarrier.init.shared.b64 [%0], %1;" :: "r"((uint32_t)(mbar)), "r"((uint32_t)(cnt)) : "memory")

__device__ __forceinline__ void mbar_wait(uint32_t mbar, uint32_t parity) {
    uint32_t done;
    asm volatile("{\n\t.reg .pred p;\n\t"
                 "mbarrier.try_wait.parity.acquire.cta.shared::cta.b64 p, [%1], %2;\n\t"
                 "selp.b32 %0, 1, 0, p;\n\t}"
                 : "=r"(done) : "r"(mbar), "r"(parity) : "memory");
    if (!done) {
        asm volatile("{\n\t.reg .pred P1;\n\t"
                     "W0_%=:\n\t"
                     "mbarrier.try_wait.parity.acquire.cta.shared::cta.b64 P1, [%0], %1, 0x989680;\n\t"
                     "@P1 bra.uni W1_%=;\n\t"
                     "bra.uni W0_%=;\n\t"
                     "W1_%=:\n\t}"
                     :: "r"(mbar), "r"(parity) : "memory");
    }
}

#define TC_LD_X32(r, addr) \
    asm volatile("tcgen05.ld.sync.aligned.32x32b.x32.b32 " \
        "{%0, %1, %2, %3, %4, %5, %6, %7, %8, %9, %10, %11, %12, %13, %14, %15, " \
        " %16, %17, %18, %19, %20, %21, %22, %23, %24, %25, %26, %27, %28, %29, %30, %31}, [%32];" \
        : "=r"((r)[0]),  "=r"((r)[1]),  "=r"((r)[2]),  "=r"((r)[3]), \
          "=r"((r)[4]),  "=r"((r)[5]),  "=r"((r)[6]),  "=r"((r)[7]), \
          "=r"((r)[8]),  "=r"((r)[9]),  "=r"((r)[10]), "=r"((r)[11]), \
          "=r"((r)[12]), "=r"((r)[13]), "=r"((r)[14]), "=r"((r)[15]), \
          "=r"((r)[16]), "=r"((r)[17]), "=r"((r)[18]), "=r"((r)[19]), \
          "=r"((r)[20]), "=r"((r)[21]), "=r"((r)[22]), "=r"((r)[23]), \
          "=r"((r)[24]), "=r"((r)[25]), "=r"((r)[26]), "=r"((r)[27]), \
          "=r"((r)[28]), "=r"((r)[29]), "=r"((r)[30]), "=r"((r)[31]) \
        : "r"(addr))

#define TC_ST_X32(addr, r) \
    asm volatile("tcgen05.st.sync.aligned.32x32b.x32.b32 [%0], " \
        "{%1, %2, %3, %4, %5, %6, %7, %8, %9, %10, %11, %12, %13, %14, %15, %16, " \
        " %17, %18, %19, %20, %21, %22, %23, %24, %25, %26, %27, %28, %29, %30, %31, %32};" \
        :: "r"(addr), \
           "r"((r)[0]),  "r"((r)[1]),  "r"((r)[2]),  "r"((r)[3]), \
           "r"((r)[4]),  "r"((r)[5]),  "r"((r)[6]),  "r"((r)[7]), \
           "r"((r)[8]),  "r"((r)[9]),  "r"((r)[10]), "r"((r)[11]), \
           "r"((r)[12]), "r"((r)[13]), "r"((r)[14]), "r"((r)[15]), \
           "r"((r)[16]), "r"((r)[17]), "r"((r)[18]), "r"((r)[19]), \
           "r"((r)[20]), "r"((r)[21]), "r"((r)[22]), "r"((r)[23]), \
           "r"((r)[24]), "r"((r)[25]), "r"((r)[26]), "r"((r)[27]), \
           "r"((r)[28]), "r"((r)[29]), "r"((r)[30]), "r"((r)[31]) \
        : "memory")

__device__ __forceinline__ void mma_tf32_ss(uint32_t d, uint64_t ad, uint64_t bd,
                                            uint32_t idesc, bool acc) {
    uint32_t en = acc ? 1u : 0u;
    asm volatile("{\n\t.reg .pred p;\n\tsetp.ne.u32 p, %5, 0;\n\t"
                 "tcgen05.mma.cta_group::1.kind::tf32 [%0], %1, %2, %3, {%4, %4, %4, %4}, p;\n\t}"
                 :: "r"(d), "l"(ad), "l"(bd), "r"(idesc), "r"(0u), "r"(en) : "memory");
}
__device__ __forceinline__ void mma_tf32_ts(uint32_t d, uint32_t a, uint64_t bd,
                                            uint32_t idesc, bool acc) {
    uint32_t en = acc ? 1u : 0u;
    asm volatile("{\n\t.reg .pred p;\n\tsetp.ne.u32 p, %5, 0;\n\t"
                 "tcgen05.mma.cta_group::1.kind::tf32 [%0], [%1], %2, %3, {%4, %4, %4, %4}, p;\n\t}"
                 :: "r"(d), "r"(a), "l"(bd), "r"(idesc), "r"(0u), "r"(en) : "memory");
}

__device__ __forceinline__ uint64_t make_desc(uint32_t addr) {
    const uint64_t base = (uint64_t(2) << 61) | (uint64_t(1) << 46)
                        | (uint64_t(64) << 32) | (uint64_t(1) << 16);
    return base | ((uint64_t)(addr >> 4) & 0x3FFF);
}
__device__ __forceinline__ uint32_t toff(int r, int k, int R) {
    uint32_t b = ((uint32_t)((r >> 3) + (k >> 5) * R) << 10) + ((r & 7) << 7)
               + ((uint32_t)(k & 31) << 2);
    return b ^ ((b >> 3) & 0x70);
}
#define IDESC(M, N) ((1u << 4) | (2u << 7) | (2u << 10) | ((uint32_t)((N) / 8) << 17) | ((uint32_t)((M) / 16) << 24))
#endif  // HAS_TCGEN05

// ---------------------------------------------------------------------------
// GroupNorm stats: per (b,g): scale[c]=w[c]*rstd, shift[c]=b[c]-mean*scale[c]
// ---------------------------------------------------------------------------
__global__ void __launch_bounds__(256) gn_stats_kernel(
    const float* __restrict__ x, const float* __restrict__ w,
    const float* __restrict__ bvec, float* __restrict__ oscale,
    float* __restrict__ oshift)
{
    const int grp = blockIdx.x;
    const float* xg = x + (size_t)grp * CPG * TT;

    float s = 0.f, ss = 0.f;
    for (int i = threadIdx.x * 4; i < CPG * TT; i += 1024) {
        float4 v = *(const float4*)(xg + i);
        s  += v.x + v.y + v.z + v.w;
        ss += v.x * v.x + v.y * v.y + v.z * v.z + v.w * v.w;
    }
    __shared__ float rs[8], rss[8];
    #pragma unroll
    for (int o = 16; o > 0; o >>= 1) {
        s  += __shfl_xor_sync(0xffffffffu, s, o);
        ss += __shfl_xor_sync(0xffffffffu, ss, o);
    }
    const int warp = threadIdx.x >> 5, lane = threadIdx.x & 31;
    if (lane == 0) { rs[warp] = s; rss[warp] = ss; }
    __syncthreads();
    if (threadIdx.x < 16) {
        float a = 0.f, b2 = 0.f;
        #pragma unroll
        for (int i = 0; i < 8; i++) { a += rs[i]; b2 += rss[i]; }
        const float inv_n = 1.f / (float)(CPG * TT);
        const float mean = a * inv_n;
        const float var  = b2 * inv_n - mean * mean;
        const float rstd = rsqrtf(var + 1e-5f);
        const int b = grp >> 5;
        const int c = (grp & 31) * CPG + threadIdx.x;
        const float sc = w[c] * rstd;
        oscale[b * CC + c] = sc;
        oshift[b * CC + c] = bvec[c] - mean * sc;
    }
}

// ---------------------------------------------------------------------------
// tf32 tcgen05 GEMM (R13-exact 256-thread mainloop/epilogue) + optional fused GN
// ---------------------------------------------------------------------------
template <bool RESID, int MT, bool FUSE_GN>
__global__ void __launch_bounds__(256) gemm_tc(
    const float* __restrict__ A, const float* __restrict__ Bm,
    const float* __restrict__ gsc, const float* __restrict__ gsh,
    const float* __restrict__ bias, const float* __restrict__ resid,
    float* __restrict__ C, int M, int K)
{
#if HAS_TCGEN05
    extern __shared__ char dsm_raw[];
    const uint32_t sraw = smem_u32(dsm_raw);
    const uint32_t sal = (sraw + 1023) & ~1023u;
    char* smb = dsm_raw + (sal - sraw);
    const uint32_t ABYTES = MT * 16384;
    const uint32_t BUFBYTES = ABYTES + 32768;
    const uint32_t Aaddr[2]  = { sal,              sal + BUFBYTES };
    const uint32_t B0addr[2] = { sal + ABYTES,     sal + BUFBYTES + ABYTES };
    const uint32_t B1addr[2] = { sal + ABYTES + 16384, sal + BUFBYTES + ABYTES + 16384 };

    __shared__ uint32_t s_tmem;
    __shared__ __align__(8) uint64_t s_mbar[2];

    const int tid = threadIdx.x;
    const int wid = tid >> 5;
    const int lane = tid & 31;
    const int n0 = blockIdx.x * 256;
    const int m0 = blockIdx.y * (MT * 128);
    const int bz = blockIdx.z;
    Bm += (size_t)bz * K * TT;
    C  += (size_t)bz * M * TT;
    const float* rp = RESID ? resid + (size_t)bz * M * TT : nullptr;
    const float* scp = FUSE_GN ? gsc + bz * CC : nullptr;
    const float* shp = FUSE_GN ? gsh + bz * CC : nullptr;

    if (wid == 0) TC_ALLOC(smem_u32(&s_tmem), MT * 256);
    if (tid == 0) { MBAR_INIT(smem_u32(&s_mbar[0]), 1); MBAR_INIT(smem_u32(&s_mbar[1]), 1); }
    __syncthreads();
    uint32_t tmem;
    asm volatile("ld.shared.b32 %0, [%1];" : "=r"(tmem) : "r"(smem_u32(&s_tmem)));
    const uint32_t mbar[2] = { smem_u32(&s_mbar[0]), smem_u32(&s_mbar[1]) };
    const uint32_t idesc = IDESC(128, 128);
    const int nk = K / 32;

    for (int i = 0; i < nk; i++) {
        const int bsel = i & 1;
        if (i >= 2) mbar_wait(mbar[bsel], (uint32_t)(((i >> 1) - 1) & 1));

        {   // stage A: MT tiles [128m x 32k] (R13 layout)
            const int row = tid >> 1;
            const int kk = (tid & 1) * 16;
            #pragma unroll
            for (int mi = 0; mi < MT; mi++) {
                const float* Ak = A + (size_t)(m0 + mi * 128 + row) * K + i * 32 + kk;
                char* ab = dsm_raw + (Aaddr[bsel] - sraw) + mi * 16384;
                #pragma unroll
                for (int u = 0; u < 4; u++) {
                    const float4 v = *(const float4*)&Ak[u * 4];
                    *(float4*)(ab + toff(row, kk + u * 4, 16)) = v;
                }
            }
        }
        {   // stage B halves [128n x 32k] via transpose (R13 layout) + fused GN
            const int krow = tid >> 3;
            const float* Bk = Bm + (size_t)(i * 32 + krow) * TT + n0;
            char* bb0 = dsm_raw + (B0addr[bsel] - sraw);
            char* bb1 = dsm_raw + (B1addr[bsel] - sraw);
            float sc = 1.f, sh = 0.f;
            if (FUSE_GN) {
                const int c = i * 32 + krow;
                sc = scp[c]; sh = shp[c];
            }
            #pragma unroll
            for (int p = 0; p < 4; p++) {
                const int nn = (tid & 7) * 4 + p * 32;
                float4 v0 = *(const float4*)&Bk[nn];
                float4 v1 = *(const float4*)&Bk[nn + 128];
                if (FUSE_GN) {
                    v0.x = v0.x * sc + sh; v0.y = v0.y * sc + sh;
                    v0.z = v0.z * sc + sh; v0.w = v0.w * sc + sh;
                    v1.x = v1.x * sc + sh; v1.y = v1.y * sc + sh;
                    v1.z = v1.z * sc + sh; v1.w = v1.w * sc + sh;
                }
                *(float*)(bb0 + toff(nn + 0, krow, 16)) = v0.x;
                *(float*)(bb0 + toff(nn + 1, krow, 16)) = v0.y;
                *(float*)(bb0 + toff(nn + 2, krow, 16)) = v0.z;
                *(float*)(bb0 + toff(nn + 3, krow, 16)) = v0.w;
                *(float*)(bb1 + toff(nn + 0, krow, 16)) = v1.x;
                *(float*)(bb1 + toff(nn + 1, krow, 16)) = v1.y;
                *(float*)(bb1 + toff(nn + 2, krow, 16)) = v1.z;
                *(float*)(bb1 + toff(nn + 3, krow, 16)) = v1.w;
            }
        }
        __syncthreads();
        if (wid == 0 && elect_one()) {
            const uint64_t bd0 = make_desc(B0addr[bsel]);
            const uint64_t bd1 = make_desc(B1addr[bsel]);
            #pragma unroll
            for (int j = 0; j < 4; j++) {
                const bool acc = (i > 0) || (j > 0);
                #pragma unroll
                for (int mi = 0; mi < MT; mi++) {
                    const uint64_t ad = make_desc(Aaddr[bsel] + mi * 16384);
                    mma_tf32_ss(tmem + (mi * 2 + 0) * 128, ad + j * 2, bd0 + j * 2, idesc, acc);
                    mma_tf32_ss(tmem + (mi * 2 + 1) * 128, ad + j * 2, bd1 + j * 2, idesc, acc);
                }
            }
            TC_COMMIT(mbar[bsel]);
        }
        __syncthreads();
    }
    mbar_wait(mbar[(nk - 1) & 1], (uint32_t)(((nk - 1) >> 1) & 1));
    TC_FENCE_AFTER();
    __syncthreads();

    // epilogue (R13-exact): MT m-tiles x 2 n-halves x 2 iterations
    const int wg = wid >> 2;
    const int sp = wid & 3;
    const uint32_t woff = (uint32_t)sp << 21;
    const int wg_tid = tid & 127;
    float* tsm = (float*)smb;
    const int wbase = wg * 32 * 133;

    #pragma unroll
    for (int mi = 0; mi < MT; mi++) {
        for (int h2 = 0; h2 < 2; h2++) {
            for (int it = 0; it < 2; it++) {
                const int c4 = it * 2 + wg;
                uint32_t regs[32];
                TC_LD_X32(regs, tmem + (mi * 2 + h2) * 128 + c4 * 32 + woff);
                TC_WAIT_LD();
                const int myrow = sp * 32 + lane;
                #pragma unroll
                for (int j = 0; j < 32; j++) tsm[wbase + j * 133 + myrow] = __uint_as_float(regs[j]);
                __syncthreads();
                const int n = wg_tid & 31;
                #pragma unroll
                for (int q = 0; q < 32; q++) {
                    const int m = (wg_tid >> 5) + q * 4;
                    float v = tsm[wbase + n * 133 + m] + bias[m0 + mi * 128 + m];
                    const size_t off = (size_t)(m0 + mi * 128 + m) * TT + n0 + h2 * 128 + c4 * 32 + n;
                    if (RESID) v += rp[off];
                    C[off] = v;
                }
                __syncthreads();
            }
        }
    }
    if (wid == 0) { TC_RELINQ(); TC_DEALLOC(tmem, MT * 256); }
#endif
}

// ---------------------------------------------------------------------------
// Single-pass flash attention (exact R11/R13-passing version)
// ---------------------------------------------------------------------------
__global__ void __launch_bounds__(256, 2) attn_tc(
    const float* __restrict__ qkv, float* __restrict__ a_out)
{
#if HAS_TCGEN05
    extern __shared__ char dsm_raw[];
    const uint32_t sraw = smem_u32(dsm_raw);
    const uint32_t sal = (sraw + 1023) & ~1023u;
    char* smb = dsm_raw + (sal - sraw);
    char* Kb = smb;
    char* Vb[2] = { smb + 32768, smb + 65536 };
    const uint32_t Kaddr = sal;
    const uint32_t Vaddr[2] = { sal + 32768, sal + 65536 };

    __shared__ uint32_t s_tmem;
    __shared__ __align__(8) uint64_t s_mbar[2];
    __shared__ float pmax[2][128], psum[2][128];
    __shared__ float m_s[128], l_s[128];

    const int tid = threadIdx.x;
    const int wid = tid >> 5;
    const int lane = tid & 31;
    const int sp = wid & 3;
    const int wg = wid >> 2;
    const uint32_t woff = (uint32_t)sp << 21;
    const int row = sp * 32 + lane;

    const int bh = blockIdx.y;
    const int b = bh >> 3, h = bh & 7;
    const int t0 = blockIdx.x * 128;

    const float* qp = qkv + ((size_t)(b * 3 * CC) + (size_t)h * 3 * CHH) * TT;
    const float* kp = qp + (size_t)CHH * TT;
    const float* vp = qp + (size_t)2 * CHH * TT;

    if (wid == 0) TC_ALLOC(smem_u32(&s_tmem), 256);
    if (tid == 0) { MBAR_INIT(smem_u32(&s_mbar[0]), 1); MBAR_INIT(smem_u32(&s_mbar[1]), 1); }
    if (wg == 0) { m_s[row] = -1e30f; l_s[row] = 0.f; }
    __syncthreads();
    uint32_t tmem;
    asm volatile("ld.shared.b32 %0, [%1];" : "=r"(tmem) : "r"(smem_u32(&s_tmem)));
    const uint32_t mb = smem_u32(&s_mbar[0]);
    const uint32_t mb2 = smem_u32(&s_mbar[1]);
    const uint32_t tS = tmem, tO = tmem + 128, tQ = tmem + 192;
    const uint32_t idS = IDESC(128, 128);
    const uint32_t idO = IDESC(128, 64);

    {
        uint32_t qreg[32];
        #pragma unroll
        for (int j = 0; j < 32; j++) {
            const int c = wg * 32 + j;
            qreg[j] = __float_as_uint(qp[(size_t)c * TT + t0 + row] * 0.125f);
        }
        TC_ST_X32(tQ + wg * 32 + woff, qreg);
        TC_WAIT_ST();
        TC_FENCE_BEFORE();
    }

    const uint64_t kdesc = make_desc(Kaddr);
    const uint64_t vdesc[2] = { make_desc(Vaddr[0]), make_desc(Vaddr[1]) };

    for (int st = 0; st < 8; st++) {
        const int s0 = st * 128;
        {
            const int c = tid >> 2;
            char* vb = Vb[st & 1];
            #pragma unroll
            for (int p = 0; p < 8; p++) {
                const int s = (tid & 3) * 4 + p * 16;
                const float4 v = *(const float4*)&kp[(size_t)c * TT + s0 + s];
                *(float*)(Kb + toff(s + 0, c, 16)) = v.x;
                *(float*)(Kb + toff(s + 1, c, 16)) = v.y;
                *(float*)(Kb + toff(s + 2, c, 16)) = v.z;
                *(float*)(Kb + toff(s + 3, c, 16)) = v.w;
                const float4 w = *(const float4*)&vp[(size_t)c * TT + s0 + s];
                *(float4*)(vb + toff(c, s, 8)) = w;
            }
        }
        __syncthreads();
        if (wid == 0 && elect_one()) {
            TC_FENCE_AFTER();
            if (st > 0) mbar_wait(mb2, (uint32_t)((st - 1) & 1));
            #pragma unroll
            for (int j = 0; j < 8; j++) {
                const uint64_t off = (uint64_t)((j & 3) * 2 + (j >> 2) * 1024);
                mma_tf32_ts(tS, tQ + j * 8, kdesc + off, idS, j > 0);
            }
            TC_COMMIT(mb);
        }
        mbar_wait(mb, (uint32_t)(st & 1));
        TC_FENCE_AFTER();

        uint32_t r0[32], r1[32];
        TC_LD_X32(r0, tS + wg * 64 + woff);
        TC_LD_X32(r1, tS + wg * 64 + 32 + woff);
        TC_WAIT_LD();
        float pm = -1e30f;
        #pragma unroll
        for (int j = 0; j < 32; j++) {
            pm = fmaxf(pm, __uint_as_float(r0[j]));
            pm = fmaxf(pm, __uint_as_float(r1[j]));
        }
        pmax[wg][row] = pm;
        __syncthreads();
        const float mold = m_s[row];
        const float mnew = fmaxf(mold, fmaxf(pmax[0][row], pmax[1][row]));
        const float alpha = __expf(mold - mnew);
        float psumv = 0.f;
        #pragma unroll
        for (int j = 0; j < 32; j++) {
            float v0 = __expf(__uint_as_float(r0[j]) - mnew);
            float v1 = __expf(__uint_as_float(r1[j]) - mnew);
            psumv += v0 + v1;
            r0[j] = __float_as_uint(v0);
            r1[j] = __float_as_uint(v1);
        }
        psum[wg][row] = psumv;
        TC_ST_X32(tS + wg * 64 + woff, r0);
        TC_ST_X32(tS + wg * 64 + 32 + woff, r1);
        if (st > 0) {
            uint32_t o[32];
            TC_LD_X32(o, tO + wg * 32 + woff);
            TC_WAIT_LD();
            #pragma unroll
            for (int j = 0; j < 32; j++)
                o[j] = __float_as_uint(__uint_as_float(o[j]) * alpha);
            TC_ST_X32(tO + wg * 32 + woff, o);
        }
        TC_WAIT_ST();
        TC_FENCE_BEFORE();
        __syncthreads();
        if (wg == 0) {
            l_s[row] = l_s[row] * alpha + psum[0][row] + psum[1][row];
            m_s[row] = mnew;
        }
        if (wid == 0 && elect_one()) {
            TC_FENCE_AFTER();
            #pragma unroll
            for (int j = 0; j < 16; j++) {
                const uint64_t off = (uint64_t)((j & 3) * 2 + (j >> 2) * 512);
                mma_tf32_ts(tO, tS + j * 8, vdesc[st & 1] + off, idO,
                            (st > 0) || (j > 0));
            }
            TC_COMMIT(mb2);
        }
    }

    mbar_wait(mb2, 1u);
    TC_FENCE_AFTER();
    __syncthreads();

    {
        uint32_t o[32];
        TC_LD_X32(o, tO + wg * 32 + woff);
        TC_WAIT_LD();
        const float inv = 1.f / l_s[row];
        float* ao = a_out + ((size_t)(b * CC) + (size_t)h * CHH) * TT + t0;
        #pragma unroll
        for (int j = 0; j < 32; j++)
            ao[(size_t)(wg * 32 + j) * TT + row] = __uint_as_float(o[j]) * inv;
    }
    __syncthreads();
    if (wid == 0) { TC_RELINQ(); TC_DEALLOC(tmem, 256); }
#endif
}

// ---------------------------------------------------------------------------
extern "C" void kernel_launch(void* const* d_in, const int* in_sizes, int n_in,
                              void* d_out, int out_size)
{
    const float* x      = (const float*)d_in[0];
    const float* norm_w = (const float*)d_in[1];
    const float* norm_b = (const float*)d_in[2];
    const float* qkv_w  = (const float*)d_in[3];
    const float* qkv_b  = (const float*)d_in[4];
    const float* proj_w = (const float*)d_in[5];
    const float* proj_b = (const float*)d_in[6];
    float* out = (float*)d_out;

    float *qkv_buf, *a_buf, *sc_buf, *sh_buf;
    cudaGetSymbolAddress((void**)&qkv_buf, g_qkv);
    cudaGetSymbolAddress((void**)&a_buf, g_a);
    cudaGetSymbolAddress((void**)&sc_buf, g_scale);
    cudaGetSymbolAddress((void**)&sh_buf, g_shift);

    const int GEMM1_SMEM = 99328;    // MT=1: 96KB + pad
    const int GEMM2_SMEM = 132096;   // MT=2: 128KB + pad
    const int ATTN_SMEM = 99328;
    cudaFuncSetAttribute(gemm_tc<false, 2, true>, cudaFuncAttributeMaxDynamicSharedMemorySize, GEMM2_SMEM);
    cudaFuncSetAttribute(gemm_tc<true, 1, false>, cudaFuncAttributeMaxDynamicSharedMemorySize, GEMM1_SMEM);
    cudaFuncSetAttribute(attn_tc, cudaFuncAttributeMaxDynamicSharedMemorySize, ATTN_SMEM);

    // 1. GN stats (scale/shift tables only)
    gn_stats_kernel<<<BB * NG, 256>>>(x, norm_w, norm_b, sc_buf, sh_buf);
    // 2. QKV GEMM with fused GN on the B side (reads x directly)
    gemm_tc<false, 2, true><<<dim3(TT / 256, 3 * CC / 256, BB), 256, GEMM2_SMEM>>>(
        qkv_w, x, sc_buf, sh_buf, qkv_b, nullptr, qkv_buf, 3 * CC, CC);
    // 3. Attention
    attn_tc<<<dim3(TT / 128, BB * NHH), 256, ATTN_SMEM>>>(qkv_buf, a_buf);
    // 4. Proj + bias + residual
    gemm_tc<true, 1, false><<<dim3(TT / 256, CC / 128, BB), 256, GEMM1_SMEM>>>(
        proj_w, a_buf, nullptr, nullptr, proj_b, x, out, CC, CC);
}

// round 16
// speedup vs baseline: 1.0401x; 1.0401x over previous
#include <cuda_runtime.h>
#include <cstdint>

#define BB   8
#define CC   512
#define TT   1024
#define NHH  8
#define CHH  64
#define NG   32
#define CPG  16

#if (defined(__CUDA_ARCH_FEAT_SM103_ALL) || defined(__CUDA_ARCH_FEAT_SM100_ALL) || defined(__CUDA_ARCH_FEAT_SM110_ALL))
#define HAS_TCGEN05 1
#else
#define HAS_TCGEN05 0
#endif

__device__ float g_qkv[BB * 3 * CC * TT];
__device__ float g_a[BB * CC * TT];
__device__ float g_scale[BB * CC];
__device__ float g_shift[BB * CC];

__device__ __forceinline__ uint32_t smem_u32(const void* p) {
    uint32_t a;
    asm("{ .reg .u64 t; cvta.to.shared.u64 t, %1; cvt.u32.u64 %0, t; }" : "=r"(a) : "l"(p));
    return a;
}
#if HAS_TCGEN05
__device__ __forceinline__ uint32_t elect_one() {
    uint32_t pred;
    asm volatile("{\n\t.reg .pred p;\n\telect.sync _|p, 0xFFFFFFFF;\n\t"
                 "selp.b32 %0, 1, 0, p;\n\t}" : "=r"(pred));
    return pred;
}
#define TC_ALLOC(smem_addr, n) \
    asm volatile("tcgen05.alloc.cta_group::1.sync.aligned.shared::cta.b32 [%0], %1;" \
                 :: "r"((uint32_t)(smem_addr)), "r"((uint32_t)(n)) : "memory")
#define TC_DEALLOC(tmem, n) \
    asm volatile("tcgen05.dealloc.cta_group::1.sync.aligned.b32 %0, %1;" :: "r"(tmem), "r"((uint32_t)(n)))
#define TC_RELINQ() asm volatile("tcgen05.relinquish_alloc_permit.cta_group::1.sync.aligned;")
#define TC_COMMIT(mbar) \
    asm volatile("tcgen05.commit.cta_group::1.mbarrier::arrive::one.shared::cluster.b64 [%0];" \
                 :: "r"((uint32_t)(mbar)) : "memory")
#define TC_FENCE_BEFORE() asm volatile("tcgen05.fence::before_thread_sync;" ::: "memory")
#define TC_FENCE_AFTER()  asm volatile("tcgen05.fence::after_thread_sync;" ::: "memory")
#define TC_WAIT_LD() asm volatile("tcgen05.wait::ld.sync.aligned;" ::: "memory")
#define TC_WAIT_ST() asm volatile("tcgen05.wait::st.sync.aligned;" ::: "memory")
#define MBAR_INIT(mbar, cnt) \
    asm volatile("mbarrier.init.shared.b64 [%0], %1;" :: "r"((uint32_t)(mbar)), "r"((uint32_t)(cnt)) : "memory")

__device__ __forceinline__ void mbar_wait(uint32_t mbar, uint32_t parity) {
    uint32_t done;
    asm volatile("{\n\t.reg .pred p;\n\t"
                 "mbarrier.try_wait.parity.acquire.cta.shared::cta.b64 p, [%1], %2;\n\t"
                 "selp.b32 %0, 1, 0, p;\n\t}"
                 : "=r"(done) : "r"(mbar), "r"(parity) : "memory");
    if (!done) {
        asm volatile("{\n\t.reg .pred P1;\n\t"
                     "W0_%=:\n\t"
                     "mbarrier.try_wait.parity.acquire.cta.shared::cta.b64 P1, [%0], %1, 0x989680;\n\t"
                     "@P1 bra.uni W1_%=;\n\t"
                     "bra.uni W0_%=;\n\t"
                     "W1_%=:\n\t}"
                     :: "r"(mbar), "r"(parity) : "memory");
    }
}

#define TC_LD_X32(r, addr) \
    asm volatile("tcgen05.ld.sync.aligned.32x32b.x32.b32 " \
        "{%0, %1, %2, %3, %4, %5, %6, %7, %8, %9, %10, %11, %12, %13, %14, %15, " \
        " %16, %17, %18, %19, %20, %21, %22, %23, %24, %25, %26, %27, %28, %29, %30, %31}, [%32];" \
        : "=r"((r)[0]),  "=r"((r)[1]),  "=r"((r)[2]),  "=r"((r)[3]), \
          "=r"((r)[4]),  "=r"((r)[5]),  "=r"((r)[6]),  "=r"((r)[7]), \
          "=r"((r)[8]),  "=r"((r)[9]),  "=r"((r)[10]), "=r"((r)[11]), \
          "=r"((r)[12]), "=r"((r)[13]), "=r"((r)[14]), "=r"((r)[15]), \
          "=r"((r)[16]), "=r"((r)[17]), "=r"((r)[18]), "=r"((r)[19]), \
          "=r"((r)[20]), "=r"((r)[21]), "=r"((r)[22]), "=r"((r)[23]), \
          "=r"((r)[24]), "=r"((r)[25]), "=r"((r)[26]), "=r"((r)[27]), \
          "=r"((r)[28]), "=r"((r)[29]), "=r"((r)[30]), "=r"((r)[31]) \
        : "r"(addr))

#define TC_ST_X32(addr, r) \
    asm volatile("tcgen05.st.sync.aligned.32x32b.x32.b32 [%0], " \
        "{%1, %2, %3, %4, %5, %6, %7, %8, %9, %10, %11, %12, %13, %14, %15, %16, " \
        " %17, %18, %19, %20, %21, %22, %23, %24, %25, %26, %27, %28, %29, %30, %31, %32};" \
        :: "r"(addr), \
           "r"((r)[0]),  "r"((r)[1]),  "r"((r)[2]),  "r"((r)[3]), \
           "r"((r)[4]),  "r"((r)[5]),  "r"((r)[6]),  "r"((r)[7]), \
           "r"((r)[8]),  "r"((r)[9]),  "r"((r)[10]), "r"((r)[11]), \
           "r"((r)[12]), "r"((r)[13]), "r"((r)[14]), "r"((r)[15]), \
           "r"((r)[16]), "r"((r)[17]), "r"((r)[18]), "r"((r)[19]), \
           "r"((r)[20]), "r"((r)[21]), "r"((r)[22]), "r"((r)[23]), \
           "r"((r)[24]), "r"((r)[25]), "r"((r)[26]), "r"((r)[27]), \
           "r"((r)[28]), "r"((r)[29]), "r"((r)[30]), "r"((r)[31]) \
        : "memory")

__device__ __forceinline__ void mma_tf32_ss(uint32_t d, uint64_t ad, uint64_t bd,
                                            uint32_t idesc, bool acc) {
    uint32_t en = acc ? 1u : 0u;
    asm volatile("{\n\t.reg .pred p;\n\tsetp.ne.u32 p, %5, 0;\n\t"
                 "tcgen05.mma.cta_group::1.kind::tf32 [%0], %1, %2, %3, {%4, %4, %4, %4}, p;\n\t}"
                 :: "r"(d), "l"(ad), "l"(bd), "r"(idesc), "r"(0u), "r"(en) : "memory");
}
__device__ __forceinline__ void mma_tf32_ts(uint32_t d, uint32_t a, uint64_t bd,
                                            uint32_t idesc, bool acc) {
    uint32_t en = acc ? 1u : 0u;
    asm volatile("{\n\t.reg .pred p;\n\tsetp.ne.u32 p, %5, 0;\n\t"
                 "tcgen05.mma.cta_group::1.kind::tf32 [%0], [%1], %2, %3, {%4, %4, %4, %4}, p;\n\t}"
                 :: "r"(d), "r"(a), "l"(bd), "r"(idesc), "r"(0u), "r"(en) : "memory");
}

__device__ __forceinline__ uint64_t make_desc(uint32_t addr) {
    const uint64_t base = (uint64_t(2) << 61) | (uint64_t(1) << 46)
                        | (uint64_t(64) << 32) | (uint64_t(1) << 16);
    return base | ((uint64_t)(addr >> 4) & 0x3FFF);
}
__device__ __forceinline__ uint32_t toff(int r, int k, int R) {
    uint32_t b = ((uint32_t)((r >> 3) + (k >> 5) * R) << 10) + ((r & 7) << 7)
               + ((uint32_t)(k & 31) << 2);
    return b ^ ((b >> 3) & 0x70);
}
#define IDESC(M, N) ((1u << 4) | (2u << 7) | (2u << 10) | ((uint32_t)((N) / 8) << 17) | ((uint32_t)((M) / 16) << 24))
#endif  // HAS_TCGEN05

// ---------------------------------------------------------------------------
// GroupNorm stats
// ---------------------------------------------------------------------------
__global__ void __launch_bounds__(256) gn_stats_kernel(
    const float* __restrict__ x, const float* __restrict__ w,
    const float* __restrict__ bvec, float* __restrict__ oscale,
    float* __restrict__ oshift)
{
    const int grp = blockIdx.x;
    const float* xg = x + (size_t)grp * CPG * TT;

    float s = 0.f, ss = 0.f;
    for (int i = threadIdx.x * 4; i < CPG * TT; i += 1024) {
        float4 v = *(const float4*)(xg + i);
        s  += v.x + v.y + v.z + v.w;
        ss += v.x * v.x + v.y * v.y + v.z * v.z + v.w * v.w;
    }
    __shared__ float rs[8], rss[8];
    #pragma unroll
    for (int o = 16; o > 0; o >>= 1) {
        s  += __shfl_xor_sync(0xffffffffu, s, o);
        ss += __shfl_xor_sync(0xffffffffu, ss, o);
    }
    const int warp = threadIdx.x >> 5, lane = threadIdx.x & 31;
    if (lane == 0) { rs[warp] = s; rss[warp] = ss; }
    __syncthreads();
    if (threadIdx.x < 16) {
        float a = 0.f, b2 = 0.f;
        #pragma unroll
        for (int i = 0; i < 8; i++) { a += rs[i]; b2 += rss[i]; }
        const float inv_n = 1.f / (float)(CPG * TT);
        const float mean = a * inv_n;
        const float var  = b2 * inv_n - mean * mean;
        const float rstd = rsqrtf(var + 1e-5f);
        const int b = grp >> 5;
        const int c = (grp & 31) * CPG + threadIdx.x;
        const float sc = w[c] * rstd;
        oscale[b * CC + c] = sc;
        oshift[b * CC + c] = bvec[c] - mean * sc;
    }
}

// ---------------------------------------------------------------------------
// tf32 tcgen05 GEMM: (MT*128)m x 256n, KS k-subchunks (32 each) per stage,
// double-buffered, R15 staging per subchunk, optional fused GN.
// Buffer layout: A[mi][sub] (MT*KS x 16KB) then B[sub][half] (KS*2 x 16KB).
// ---------------------------------------------------------------------------
template <bool RESID, int MT, int KS, bool FUSE_GN>
__global__ void __launch_bounds__(256) gemm_tc(
    const float* __restrict__ A, const float* __restrict__ Bm,
    const float* __restrict__ gsc, const float* __restrict__ gsh,
    const float* __restrict__ bias, const float* __restrict__ resid,
    float* __restrict__ C, int M, int K)
{
#if HAS_TCGEN05
    extern __shared__ char dsm_raw[];
    const uint32_t sraw = smem_u32(dsm_raw);
    const uint32_t sal = (sraw + 1023) & ~1023u;
    char* smb = dsm_raw + (sal - sraw);
    const uint32_t ABYTES = MT * KS * 16384;
    const uint32_t BUFBYTES = ABYTES + KS * 32768;
    const uint32_t bufaddr[2] = { sal, sal + BUFBYTES };

    __shared__ uint32_t s_tmem;
    __shared__ __align__(8) uint64_t s_mbar[2];

    const int tid = threadIdx.x;
    const int wid = tid >> 5;
    const int lane = tid & 31;
    const int n0 = blockIdx.x * 256;
    const int m0 = blockIdx.y * (MT * 128);
    const int bz = blockIdx.z;
    Bm += (size_t)bz * K * TT;
    C  += (size_t)bz * M * TT;
    const float* rp = RESID ? resid + (size_t)bz * M * TT : nullptr;
    const float* scp = FUSE_GN ? gsc + bz * CC : nullptr;
    const float* shp = FUSE_GN ? gsh + bz * CC : nullptr;

    if (wid == 0) TC_ALLOC(smem_u32(&s_tmem), MT * 256);
    if (tid == 0) { MBAR_INIT(smem_u32(&s_mbar[0]), 1); MBAR_INIT(smem_u32(&s_mbar[1]), 1); }
    __syncthreads();
    uint32_t tmem;
    asm volatile("ld.shared.b32 %0, [%1];" : "=r"(tmem) : "r"(smem_u32(&s_tmem)));
    const uint32_t mbar[2] = { smem_u32(&s_mbar[0]), smem_u32(&s_mbar[1]) };
    const uint32_t idesc = IDESC(128, 128);
    const int nk = K / (32 * KS);

    for (int i = 0; i < nk; i++) {
        const int bsel = i & 1;
        if (i >= 2) mbar_wait(mbar[bsel], (uint32_t)(((i >> 1) - 1) & 1));
        const uint32_t base = bufaddr[bsel];
        char* basep = dsm_raw + (base - sraw);

        #pragma unroll
        for (int sub = 0; sub < KS; sub++) {
            const int k0 = (i * KS + sub) * 32;
            {   // stage A: MT tiles [128m x 32k]
                const int row = tid >> 1;
                const int kk = (tid & 1) * 16;
                #pragma unroll
                for (int mi = 0; mi < MT; mi++) {
                    const float* Ak = A + (size_t)(m0 + mi * 128 + row) * K + k0 + kk;
                    char* ab = basep + (mi * KS + sub) * 16384;
                    #pragma unroll
                    for (int u = 0; u < 4; u++) {
                        const float4 v = *(const float4*)&Ak[u * 4];
                        *(float4*)(ab + toff(row, kk + u * 4, 16)) = v;
                    }
                }
            }
            {   // stage B halves [128n x 32k] via transpose + fused GN
                const int krow = tid >> 3;
                const float* Bk = Bm + (size_t)(k0 + krow) * TT + n0;
                char* bb0 = basep + ABYTES + (sub * 2 + 0) * 16384;
                char* bb1 = basep + ABYTES + (sub * 2 + 1) * 16384;
                float sc = 1.f, sh = 0.f;
                if (FUSE_GN) {
                    const int c = k0 + krow;
                    sc = scp[c]; sh = shp[c];
                }
                #pragma unroll
                for (int p = 0; p < 4; p++) {
                    const int nn = (tid & 7) * 4 + p * 32;
                    float4 v0 = *(const float4*)&Bk[nn];
                    float4 v1 = *(const float4*)&Bk[nn + 128];
                    if (FUSE_GN) {
                        v0.x = v0.x * sc + sh; v0.y = v0.y * sc + sh;
                        v0.z = v0.z * sc + sh; v0.w = v0.w * sc + sh;
                        v1.x = v1.x * sc + sh; v1.y = v1.y * sc + sh;
                        v1.z = v1.z * sc + sh; v1.w = v1.w * sc + sh;
                    }
                    *(float*)(bb0 + toff(nn + 0, krow, 16)) = v0.x;
                    *(float*)(bb0 + toff(nn + 1, krow, 16)) = v0.y;
                    *(float*)(bb0 + toff(nn + 2, krow, 16)) = v0.z;
                    *(float*)(bb0 + toff(nn + 3, krow, 16)) = v0.w;
                    *(float*)(bb1 + toff(nn + 0, krow, 16)) = v1.x;
                    *(float*)(bb1 + toff(nn + 1, krow, 16)) = v1.y;
                    *(float*)(bb1 + toff(nn + 2, krow, 16)) = v1.z;
                    *(float*)(bb1 + toff(nn + 3, krow, 16)) = v1.w;
                }
            }
        }
        __syncthreads();
        if (wid == 0 && elect_one()) {
            #pragma unroll
            for (int sub = 0; sub < KS; sub++) {
                const uint64_t bd0 = make_desc(base + ABYTES + (sub * 2 + 0) * 16384);
                const uint64_t bd1 = make_desc(base + ABYTES + (sub * 2 + 1) * 16384);
                #pragma unroll
                for (int j = 0; j < 4; j++) {
                    const bool acc = (i > 0) || (sub > 0) || (j > 0);
                    #pragma unroll
                    for (int mi = 0; mi < MT; mi++) {
                        const uint64_t ad = make_desc(base + (mi * KS + sub) * 16384);
                        mma_tf32_ss(tmem + (mi * 2 + 0) * 128, ad + j * 2, bd0 + j * 2, idesc, acc);
                        mma_tf32_ss(tmem + (mi * 2 + 1) * 128, ad + j * 2, bd1 + j * 2, idesc, acc);
                    }
                }
            }
            TC_COMMIT(mbar[bsel]);
        }
        __syncthreads();
    }
    mbar_wait(mbar[(nk - 1) & 1], (uint32_t)(((nk - 1) >> 1) & 1));
    TC_FENCE_AFTER();
    __syncthreads();

    // epilogue (R13-exact structure)
    const int wg = wid >> 2;
    const int sp = wid & 3;
    const uint32_t woff = (uint32_t)sp << 21;
    const int wg_tid = tid & 127;
    float* tsm = (float*)smb;
    const int wbase = wg * 32 * 133;

    #pragma unroll
    for (int mi = 0; mi < MT; mi++) {
        for (int h2 = 0; h2 < 2; h2++) {
            for (int it = 0; it < 2; it++) {
                const int c4 = it * 2 + wg;
                uint32_t regs[32];
                TC_LD_X32(regs, tmem + (mi * 2 + h2) * 128 + c4 * 32 + woff);
                TC_WAIT_LD();
                const int myrow = sp * 32 + lane;
                #pragma unroll
                for (int j = 0; j < 32; j++) tsm[wbase + j * 133 + myrow] = __uint_as_float(regs[j]);
                __syncthreads();
                const int n = wg_tid & 31;
                #pragma unroll
                for (int q = 0; q < 32; q++) {
                    const int m = (wg_tid >> 5) + q * 4;
                    float v = tsm[wbase + n * 133 + m] + bias[m0 + mi * 128 + m];
                    const size_t off = (size_t)(m0 + mi * 128 + m) * TT + n0 + h2 * 128 + c4 * 32 + n;
                    if (RESID) v += rp[off];
                    C[off] = v;
                }
                __syncthreads();
            }
        }
    }
    if (wid == 0) { TC_RELINQ(); TC_DEALLOC(tmem, MT * 256); }
#endif
}

// ---------------------------------------------------------------------------
// Single-pass flash attention (exact R11/R15-passing version)
// ---------------------------------------------------------------------------
__global__ void __launch_bounds__(256, 2) attn_tc(
    const float* __restrict__ qkv, float* __restrict__ a_out)
{
#if HAS_TCGEN05
    extern __shared__ char dsm_raw[];
    const uint32_t sraw = smem_u32(dsm_raw);
    const uint32_t sal = (sraw + 1023) & ~1023u;
    char* smb = dsm_raw + (sal - sraw);
    char* Kb = smb;
    char* Vb[2] = { smb + 32768, smb + 65536 };
    const uint32_t Kaddr = sal;
    const uint32_t Vaddr[2] = { sal + 32768, sal + 65536 };

    __shared__ uint32_t s_tmem;
    __shared__ __align__(8) uint64_t s_mbar[2];
    __shared__ float pmax[2][128], psum[2][128];
    __shared__ float m_s[128], l_s[128];

    const int tid = threadIdx.x;
    const int wid = tid >> 5;
    const int lane = tid & 31;
    const int sp = wid & 3;
    const int wg = wid >> 2;
    const uint32_t woff = (uint32_t)sp << 21;
    const int row = sp * 32 + lane;

    const int bh = blockIdx.y;
    const int b = bh >> 3, h = bh & 7;
    const int t0 = blockIdx.x * 128;

    const float* qp = qkv + ((size_t)(b * 3 * CC) + (size_t)h * 3 * CHH) * TT;
    const float* kp = qp + (size_t)CHH * TT;
    const float* vp = qp + (size_t)2 * CHH * TT;

    if (wid == 0) TC_ALLOC(smem_u32(&s_tmem), 256);
    if (tid == 0) { MBAR_INIT(smem_u32(&s_mbar[0]), 1); MBAR_INIT(smem_u32(&s_mbar[1]), 1); }
    if (wg == 0) { m_s[row] = -1e30f; l_s[row] = 0.f; }
    __syncthreads();
    uint32_t tmem;
    asm volatile("ld.shared.b32 %0, [%1];" : "=r"(tmem) : "r"(smem_u32(&s_tmem)));
    const uint32_t mb = smem_u32(&s_mbar[0]);
    const uint32_t mb2 = smem_u32(&s_mbar[1]);
    const uint32_t tS = tmem, tO = tmem + 128, tQ = tmem + 192;
    const uint32_t idS = IDESC(128, 128);
    const uint32_t idO = IDESC(128, 64);

    {
        uint32_t qreg[32];
        #pragma unroll
        for (int j = 0; j < 32; j++) {
            const int c = wg * 32 + j;
            qreg[j] = __float_as_uint(qp[(size_t)c * TT + t0 + row] * 0.125f);
        }
        TC_ST_X32(tQ + wg * 32 + woff, qreg);
        TC_WAIT_ST();
        TC_FENCE_BEFORE();
    }

    const uint64_t kdesc = make_desc(Kaddr);
    const uint64_t vdesc[2] = { make_desc(Vaddr[0]), make_desc(Vaddr[1]) };

    for (int st = 0; st < 8; st++) {
        const int s0 = st * 128;
        {
            const int c = tid >> 2;
            char* vb = Vb[st & 1];
            #pragma unroll
            for (int p = 0; p < 8; p++) {
                const int s = (tid & 3) * 4 + p * 16;
                const float4 v = *(const float4*)&kp[(size_t)c * TT + s0 + s];
                *(float*)(Kb + toff(s + 0, c, 16)) = v.x;
                *(float*)(Kb + toff(s + 1, c, 16)) = v.y;
                *(float*)(Kb + toff(s + 2, c, 16)) = v.z;
                *(float*)(Kb + toff(s + 3, c, 16)) = v.w;
                const float4 w = *(const float4*)&vp[(size_t)c * TT + s0 + s];
                *(float4*)(vb + toff(c, s, 8)) = w;
            }
        }
        __syncthreads();
        if (wid == 0 && elect_one()) {
            TC_FENCE_AFTER();
            if (st > 0) mbar_wait(mb2, (uint32_t)((st - 1) & 1));
            #pragma unroll
            for (int j = 0; j < 8; j++) {
                const uint64_t off = (uint64_t)((j & 3) * 2 + (j >> 2) * 1024);
                mma_tf32_ts(tS, tQ + j * 8, kdesc + off, idS, j > 0);
            }
            TC_COMMIT(mb);
        }
        mbar_wait(mb, (uint32_t)(st & 1));
        TC_FENCE_AFTER();

        uint32_t r0[32], r1[32];
        TC_LD_X32(r0, tS + wg * 64 + woff);
        TC_LD_X32(r1, tS + wg * 64 + 32 + woff);
        TC_WAIT_LD();
        float pm = -1e30f;
        #pragma unroll
        for (int j = 0; j < 32; j++) {
            pm = fmaxf(pm, __uint_as_float(r0[j]));
            pm = fmaxf(pm, __uint_as_float(r1[j]));
        }
        pmax[wg][row] = pm;
        __syncthreads();
        const float mold = m_s[row];
        const float mnew = fmaxf(mold, fmaxf(pmax[0][row], pmax[1][row]));
        const float alpha = __expf(mold - mnew);
        float psumv = 0.f;
        #pragma unroll
        for (int j = 0; j < 32; j++) {
            float v0 = __expf(__uint_as_float(r0[j]) - mnew);
            float v1 = __expf(__uint_as_float(r1[j]) - mnew);
            psumv += v0 + v1;
            r0[j] = __float_as_uint(v0);
            r1[j] = __float_as_uint(v1);
        }
        psum[wg][row] = psumv;
        TC_ST_X32(tS + wg * 64 + woff, r0);
        TC_ST_X32(tS + wg * 64 + 32 + woff, r1);
        if (st > 0) {
            uint32_t o[32];
            TC_LD_X32(o, tO + wg * 32 + woff);
            TC_WAIT_LD();
            #pragma unroll
            for (int j = 0; j < 32; j++)
                o[j] = __float_as_uint(__uint_as_float(o[j]) * alpha);
            TC_ST_X32(tO + wg * 32 + woff, o);
        }
        TC_WAIT_ST();
        TC_FENCE_BEFORE();
        __syncthreads();
        if (wg == 0) {
            l_s[row] = l_s[row] * alpha + psum[0][row] + psum[1][row];
            m_s[row] = mnew;
        }
        if (wid == 0 && elect_one()) {
            TC_FENCE_AFTER();
            #pragma unroll
            for (int j = 0; j < 16; j++) {
                const uint64_t off = (uint64_t)((j & 3) * 2 + (j >> 2) * 512);
                mma_tf32_ts(tO, tS + j * 8, vdesc[st & 1] + off, idO,
                            (st > 0) || (j > 0));
            }
            TC_COMMIT(mb2);
        }
    }

    mbar_wait(mb2, 1u);
    TC_FENCE_AFTER();
    __syncthreads();

    {
        uint32_t o[32];
        TC_LD_X32(o, tO + wg * 32 + woff);
        TC_WAIT_LD();
        const float inv = 1.f / l_s[row];
        float* ao = a_out + ((size_t)(b * CC) + (size_t)h * CHH) * TT + t0;
        #pragma unroll
        for (int j = 0; j < 32; j++)
            ao[(size_t)(wg * 32 + j) * TT + row] = __uint_as_float(o[j]) * inv;
    }
    __syncthreads();
    if (wid == 0) { TC_RELINQ(); TC_DEALLOC(tmem, 256); }
#endif
}

// ---------------------------------------------------------------------------
extern "C" void kernel_launch(void* const* d_in, const int* in_sizes, int n_in,
                              void* d_out, int out_size)
{
    const float* x      = (const float*)d_in[0];
    const float* norm_w = (const float*)d_in[1];
    const float* norm_b = (const float*)d_in[2];
    const float* qkv_w  = (const float*)d_in[3];
    const float* qkv_b  = (const float*)d_in[4];
    const float* proj_w = (const float*)d_in[5];
    const float* proj_b = (const float*)d_in[6];
    float* out = (float*)d_out;

    float *qkv_buf, *a_buf, *sc_buf, *sh_buf;
    cudaGetSymbolAddress((void**)&qkv_buf, g_qkv);
    cudaGetSymbolAddress((void**)&a_buf, g_a);
    cudaGetSymbolAddress((void**)&sc_buf, g_scale);
    cudaGetSymbolAddress((void**)&sh_buf, g_shift);

    const int GEMM_QKV_SMEM = 132096;   // MT=2,KS=1: 128KB + pad
    const int GEMM_PRJ_SMEM = 197632;   // MT=1,KS=2: 192KB + pad
    const int ATTN_SMEM = 99328;
    cudaFuncSetAttribute((const void*)gemm_tc<false, 2, 1, true>,
                         cudaFuncAttributeMaxDynamicSharedMemorySize, GEMM_QKV_SMEM);
    cudaFuncSetAttribute((const void*)gemm_tc<true, 1, 2, false>,
                         cudaFuncAttributeMaxDynamicSharedMemorySize, GEMM_PRJ_SMEM);
    cudaFuncSetAttribute((const void*)attn_tc,
                         cudaFuncAttributeMaxDynamicSharedMemorySize, ATTN_SMEM);

    // 1. GN stats
    gn_stats_kernel<<<BB * NG, 256>>>(x, norm_w, norm_b, sc_buf, sh_buf);
    // 2. QKV GEMM with fused GN (MT=2, KS=1)
    gemm_tc<false, 2, 1, true><<<dim3(TT / 256, 3 * CC / 256, BB), 256, GEMM_QKV_SMEM>>>(
        qkv_w, x, sc_buf, sh_buf, qkv_b, nullptr, qkv_buf, 3 * CC, CC);
    // 3. Attention
    attn_tc<<<dim3(TT / 128, BB * NHH), 256, ATTN_SMEM>>>(qkv_buf, a_buf);
    // 4. Proj + bias + residual (MT=1, KS=2 -> 8 iterations)
    gemm_tc<true, 1, 2, false><<<dim3(TT / 256, CC / 128, BB), 256, GEMM_PRJ_SMEM>>>(
        proj_w, a_buf, nullptr, nullptr, proj_b, x, out, CC, CC);
}

// round 17
// speedup vs baseline: 1.1329x; 1.0892x over previous
#include <cuda_runtime.h>
#include <cstdint>

#define BB   8
#define CC   512
#define TT   1024
#define NHH  8
#define CHH  64
#define NG   32
#define CPG  16

#if (defined(__CUDA_ARCH_FEAT_SM103_ALL) || defined(__CUDA_ARCH_FEAT_SM100_ALL) || defined(__CUDA_ARCH_FEAT_SM110_ALL))
#define HAS_TCGEN05 1
#else
#define HAS_TCGEN05 0
#endif

__device__ float g_qkv[BB * 3 * CC * TT];
__device__ float g_a[BB * CC * TT];
__device__ float g_scale[BB * CC];
__device__ float g_shift[BB * CC];
__device__ float g_bx[BB * 8 * 16 * 4096];   // x-hat swizzled tiles: [b][ntile][kchunk][4096]
__device__ float g_wq[12 * 16 * 4096];       // qkv_w swizzled: [mtile][kchunk][4096]
__device__ float g_wp[4 * 16 * 4096];        // proj_w swizzled

__device__ __forceinline__ uint32_t smem_u32(const void* p) {
    uint32_t a;
    asm("{ .reg .u64 t; cvta.to.shared.u64 t, %1; cvt.u32.u64 %0, t; }" : "=r"(a) : "l"(p));
    return a;
}
// Blocked-atom SW128 byte offset: atom = 8 rows x 32 floats (host-independent helper)
__device__ __forceinline__ uint32_t toff(int r, int k, int R) {
    uint32_t b = ((uint32_t)((r >> 3) + (k >> 5) * R) << 10) + ((r & 7) << 7)
               + ((uint32_t)(k & 31) << 2);
    return b ^ ((b >> 3) & 0x70);
}
#if HAS_TCGEN05
__device__ __forceinline__ uint32_t elect_one() {
    uint32_t pred;
    asm volatile("{\n\t.reg .pred p;\n\telect.sync _|p, 0xFFFFFFFF;\n\t"
                 "selp.b32 %0, 1, 0, p;\n\t}" : "=r"(pred));
    return pred;
}
#define TC_ALLOC(smem_addr, n) \
    asm volatile("tcgen05.alloc.cta_group::1.sync.aligned.shared::cta.b32 [%0], %1;" \
                 :: "r"((uint32_t)(smem_addr)), "r"((uint32_t)(n)) : "memory")
#define TC_DEALLOC(tmem, n) \
    asm volatile("tcgen05.dealloc.cta_group::1.sync.aligned.b32 %0, %1;" :: "r"(tmem), "r"((uint32_t)(n)))
#define TC_RELINQ() asm volatile("tcgen05.relinquish_alloc_permit.cta_group::1.sync.aligned;")
#define TC_COMMIT(mbar) \
    asm volatile("tcgen05.commit.cta_group::1.mbarrier::arrive::one.shared::cluster.b64 [%0];" \
                 :: "r"((uint32_t)(mbar)) : "memory")
#define TC_FENCE_BEFORE() asm volatile("tcgen05.fence::before_thread_sync;" ::: "memory")
#define TC_FENCE_AFTER()  asm volatile("tcgen05.fence::after_thread_sync;" ::: "memory")
#define TC_WAIT_LD() asm volatile("tcgen05.wait::ld.sync.aligned;" ::: "memory")
#define TC_WAIT_ST() asm volatile("tcgen05.wait::st.sync.aligned;" ::: "memory")
#define MBAR_INIT(mbar, cnt) \
    asm volatile("mbarrier.init.shared.b64 [%0], %1;" :: "r"((uint32_t)(mbar)), "r"((uint32_t)(cnt)) : "memory")

__device__ __forceinline__ void mbar_wait(uint32_t mbar, uint32_t parity) {
    uint32_t done;
    asm volatile("{\n\t.reg .pred p;\n\t"
                 "mbarrier.try_wait.parity.acquire.cta.shared::cta.b64 p, [%1], %2;\n\t"
                 "selp.b32 %0, 1, 0, p;\n\t}"
                 : "=r"(done) : "r"(mbar), "r"(parity) : "memory");
    if (!done) {
        asm volatile("{\n\t.reg .pred P1;\n\t"
                     "W0_%=:\n\t"
                     "mbarrier.try_wait.parity.acquire.cta.shared::cta.b64 P1, [%0], %1, 0x989680;\n\t"
                     "@P1 bra.uni W1_%=;\n\t"
                     "bra.uni W0_%=;\n\t"
                     "W1_%=:\n\t}"
                     :: "r"(mbar), "r"(parity) : "memory");
    }
}

#define TC_LD_X32(r, addr) \
    asm volatile("tcgen05.ld.sync.aligned.32x32b.x32.b32 " \
        "{%0, %1, %2, %3, %4, %5, %6, %7, %8, %9, %10, %11, %12, %13, %14, %15, " \
        " %16, %17, %18, %19, %20, %21, %22, %23, %24, %25, %26, %27, %28, %29, %30, %31}, [%32];" \
        : "=r"((r)[0]),  "=r"((r)[1]),  "=r"((r)[2]),  "=r"((r)[3]), \
          "=r"((r)[4]),  "=r"((r)[5]),  "=r"((r)[6]),  "=r"((r)[7]), \
          "=r"((r)[8]),  "=r"((r)[9]),  "=r"((r)[10]), "=r"((r)[11]), \
          "=r"((r)[12]), "=r"((r)[13]), "=r"((r)[14]), "=r"((r)[15]), \
          "=r"((r)[16]), "=r"((r)[17]), "=r"((r)[18]), "=r"((r)[19]), \
          "=r"((r)[20]), "=r"((r)[21]), "=r"((r)[22]), "=r"((r)[23]), \
          "=r"((r)[24]), "=r"((r)[25]), "=r"((r)[26]), "=r"((r)[27]), \
          "=r"((r)[28]), "=r"((r)[29]), "=r"((r)[30]), "=r"((r)[31]) \
        : "r"(addr))

#define TC_ST_X32(addr, r) \
    asm volatile("tcgen05.st.sync.aligned.32x32b.x32.b32 [%0], " \
        "{%1, %2, %3, %4, %5, %6, %7, %8, %9, %10, %11, %12, %13, %14, %15, %16, " \
        " %17, %18, %19, %20, %21, %22, %23, %24, %25, %26, %27, %28, %29, %30, %31, %32};" \
        :: "r"(addr), \
           "r"((r)[0]),  "r"((r)[1]),  "r"((r)[2]),  "r"((r)[3]), \
           "r"((r)[4]),  "r"((r)[5]),  "r"((r)[6]),  "r"((r)[7]), \
           "r"((r)[8]),  "r"((r)[9]),  "r"((r)[10]), "r"((r)[11]), \
           "r"((r)[12]), "r"((r)[13]), "r"((r)[14]), "r"((r)[15]), \
           "r"((r)[16]), "r"((r)[17]), "r"((r)[18]), "r"((r)[19]), \
           "r"((r)[20]), "r"((r)[21]), "r"((r)[22]), "r"((r)[23]), \
           "r"((r)[24]), "r"((r)[25]), "r"((r)[26]), "r"((r)[27]), \
           "r"((r)[28]), "r"((r)[29]), "r"((r)[30]), "r"((r)[31]) \
        : "memory")

__device__ __forceinline__ void mma_tf32_ss(uint32_t d, uint64_t ad, uint64_t bd,
                                            uint32_t idesc, bool acc) {
    uint32_t en = acc ? 1u : 0u;
    asm volatile("{\n\t.reg .pred p;\n\tsetp.ne.u32 p, %5, 0;\n\t"
                 "tcgen05.mma.cta_group::1.kind::tf32 [%0], %1, %2, %3, {%4, %4, %4, %4}, p;\n\t}"
                 :: "r"(d), "l"(ad), "l"(bd), "r"(idesc), "r"(0u), "r"(en) : "memory");
}
__device__ __forceinline__ void mma_tf32_ts(uint32_t d, uint32_t a, uint64_t bd,
                                            uint32_t idesc, bool acc) {
    uint32_t en = acc ? 1u : 0u;
    asm volatile("{\n\t.reg .pred p;\n\tsetp.ne.u32 p, %5, 0;\n\t"
                 "tcgen05.mma.cta_group::1.kind::tf32 [%0], [%1], %2, %3, {%4, %4, %4, %4}, p;\n\t}"
                 :: "r"(d), "r"(a), "l"(bd), "r"(idesc), "r"(0u), "r"(en) : "memory");
}

__device__ __forceinline__ uint64_t make_desc(uint32_t addr) {
    const uint64_t base = (uint64_t(2) << 61) | (uint64_t(1) << 46)
                        | (uint64_t(64) << 32) | (uint64_t(1) << 16);
    return base | ((uint64_t)(addr >> 4) & 0x3FFF);
}
#define IDESC(M, N) ((1u << 4) | (2u << 7) | (2u << 10) | ((uint32_t)((N) / 8) << 17) | ((uint32_t)((M) / 16) << 24))
#endif  // HAS_TCGEN05

// ---------------------------------------------------------------------------
// GroupNorm stats
// ---------------------------------------------------------------------------
__global__ void __launch_bounds__(256) gn_stats_kernel(
    const float* __restrict__ x, const float* __restrict__ w,
    const float* __restrict__ bvec, float* __restrict__ oscale,
    float* __restrict__ oshift)
{
    const int grp = blockIdx.x;
    const float* xg = x + (size_t)grp * CPG * TT;

    float s = 0.f, ss = 0.f;
    for (int i = threadIdx.x * 4; i < CPG * TT; i += 1024) {
        float4 v = *(const float4*)(xg + i);
        s  += v.x + v.y + v.z + v.w;
        ss += v.x * v.x + v.y * v.y + v.z * v.z + v.w * v.w;
    }
    __shared__ float rs[8], rss[8];
    #pragma unroll
    for (int o = 16; o > 0; o >>= 1) {
        s  += __shfl_xor_sync(0xffffffffu, s, o);
        ss += __shfl_xor_sync(0xffffffffu, ss, o);
    }
    const int warp = threadIdx.x >> 5, lane = threadIdx.x & 31;
    if (lane == 0) { rs[warp] = s; rss[warp] = ss; }
    __syncthreads();
    if (threadIdx.x < 16) {
        float a = 0.f, b2 = 0.f;
        #pragma unroll
        for (int i = 0; i < 8; i++) { a += rs[i]; b2 += rss[i]; }
        const float inv_n = 1.f / (float)(CPG * TT);
        const float mean = a * inv_n;
        const float var  = b2 * inv_n - mean * mean;
        const float rstd = rsqrtf(var + 1e-5f);
        const int b = grp >> 5;
        const int c = (grp & 31) * CPG + threadIdx.x;
        const float sc = w[c] * rstd;
        oscale[b * CC + c] = sc;
        oshift[b * CC + c] = bvec[c] - mean * sc;
    }
}

// ---------------------------------------------------------------------------
// x-hat swizzle: GN(x) -> K-major SW128 tiles [b][ntile][kchunk][4096]
// block = (kc, nt, b), 128 threads
// ---------------------------------------------------------------------------
__global__ void __launch_bounds__(128) xhat_kernel(
    const float* __restrict__ x, const float* __restrict__ gsc,
    const float* __restrict__ gsh, float* __restrict__ bx)
{
    __shared__ float tile[4096];
    const int kc = blockIdx.x, nt = blockIdx.y, b = blockIdx.z;
    const int tid = threadIdx.x;
    const int krow = tid >> 2;
    const int c = kc * 32 + krow;
    const float sc = gsc[b * CC + c];
    const float sh = gsh[b * CC + c];
    const float* xp = x + ((size_t)(b * CC + c)) * TT + nt * 128;
    char* tb = (char*)tile;
    #pragma unroll
    for (int p = 0; p < 8; p++) {
        const int nn = (tid & 3) * 4 + p * 16;
        float4 v = *(const float4*)&xp[nn];
        v.x = v.x * sc + sh; v.y = v.y * sc + sh;
        v.z = v.z * sc + sh; v.w = v.w * sc + sh;
        *(float*)(tb + toff(nn + 0, krow, 16)) = v.x;
        *(float*)(tb + toff(nn + 1, krow, 16)) = v.y;
        *(float*)(tb + toff(nn + 2, krow, 16)) = v.z;
        *(float*)(tb + toff(nn + 3, krow, 16)) = v.w;
    }
    __syncthreads();
    float4* out = (float4*)(bx + ((size_t)((b * 8 + nt) * 16 + kc)) * 4096);
    const float4* in = (const float4*)tile;
    #pragma unroll
    for (int u = 0; u < 8; u++) out[u * 128 + tid] = in[u * 128 + tid];
}

// ---------------------------------------------------------------------------
// Weight swizzle: w[M,K] -> A tiles [mtile][kchunk][4096]; block=(kc, mt), 128 thr
// ---------------------------------------------------------------------------
__global__ void __launch_bounds__(128) wswz_kernel(
    const float* __restrict__ w, float* __restrict__ ws, int K)
{
    __shared__ float tile[4096];
    const int kc = blockIdx.x, mt = blockIdx.y;
    const int row = threadIdx.x;
    const float* wp = w + (size_t)(mt * 128 + row) * K + kc * 32;
    char* tb = (char*)tile;
    #pragma unroll
    for (int u = 0; u < 8; u++) {
        const float4 v = ((const float4*)wp)[u];
        *(float4*)(tb + toff(row, u * 4, 16)) = v;
    }
    __syncthreads();
    float4* out = (float4*)(ws + ((size_t)(mt * (K / 32)) + kc) * 4096);
    const float4* in = (const float4*)tile;
    #pragma unroll
    for (int u = 0; u < 8; u++) out[u * 128 + row] = in[u * 128 + row];
}

// ---------------------------------------------------------------------------
// tf32 tcgen05 GEMM: (MT*128)m x 256n, KS k-subchunks per stage, double-buffered.
// A always pre-swizzled; B pre-swizzled (BPRE) or transposed in-kernel.
// ---------------------------------------------------------------------------
template <bool RESID, int MT, int KS, bool BPRE>
__global__ void __launch_bounds__(256) gemm_tc(
    const float* __restrict__ Aw, const float* __restrict__ Bx,
    const float* __restrict__ bias, const float* __restrict__ resid,
    float* __restrict__ C, int M, int K)
{
#if HAS_TCGEN05
    extern __shared__ char dsm_raw[];
    const uint32_t sraw = smem_u32(dsm_raw);
    const uint32_t sal = (sraw + 1023) & ~1023u;
    char* smb = dsm_raw + (sal - sraw);
    const uint32_t ABYTES = MT * KS * 16384;
    const uint32_t BUFBYTES = ABYTES + KS * 32768;
    const uint32_t bufaddr[2] = { sal, sal + BUFBYTES };

    __shared__ uint32_t s_tmem;
    __shared__ __align__(8) uint64_t s_mbar[2];

    const int tid = threadIdx.x;
    const int wid = tid >> 5;
    const int lane = tid & 31;
    const int n0 = blockIdx.x * 256;
    const int m0 = blockIdx.y * (MT * 128);
    const int bz = blockIdx.z;
    const int nkc = K / 32;
    const float* Bp = BPRE ? Bx + (size_t)bz * 8 * 16 * 4096
                           : Bx + (size_t)bz * K * TT;
    C += (size_t)bz * M * TT;
    const float* rp = RESID ? resid + (size_t)bz * M * TT : nullptr;

    if (wid == 0) TC_ALLOC(smem_u32(&s_tmem), MT * 256);
    if (tid == 0) { MBAR_INIT(smem_u32(&s_mbar[0]), 1); MBAR_INIT(smem_u32(&s_mbar[1]), 1); }
    __syncthreads();
    uint32_t tmem;
    asm volatile("ld.shared.b32 %0, [%1];" : "=r"(tmem) : "r"(smem_u32(&s_tmem)));
    const uint32_t mbar[2] = { smem_u32(&s_mbar[0]), smem_u32(&s_mbar[1]) };
    const uint32_t idesc = IDESC(128, 128);
    const int nk = K / (32 * KS);

    for (int i = 0; i < nk; i++) {
        const int bsel = i & 1;
        if (i >= 2) mbar_wait(mbar[bsel], (uint32_t)(((i >> 1) - 1) & 1));
        const uint32_t base = bufaddr[bsel];
        char* basep = dsm_raw + (base - sraw);

        #pragma unroll
        for (int sub = 0; sub < KS; sub++) {
            const int kc = i * KS + sub;
            {   // A: linear tile copies (pre-swizzled)
                #pragma unroll
                for (int mi = 0; mi < MT; mi++) {
                    const float4* At = (const float4*)(Aw +
                        ((size_t)((blockIdx.y * MT + mi) * nkc + kc)) * 4096);
                    float4* ab = (float4*)(basep + (mi * KS + sub) * 16384);
                    #pragma unroll
                    for (int u = 0; u < 4; u++) ab[u * 256 + tid] = At[u * 256 + tid];
                }
            }
            if (BPRE) {   // B: linear tile copies (pre-swizzled x-hat)
                #pragma unroll
                for (int half = 0; half < 2; half++) {
                    const float4* Bt = (const float4*)(Bp +
                        ((size_t)((n0 / 128 + half) * 16 + kc)) * 4096);
                    float4* bb = (float4*)(basep + ABYTES + (sub * 2 + half) * 16384);
                    #pragma unroll
                    for (int u = 0; u < 4; u++) bb[u * 256 + tid] = Bt[u * 256 + tid];
                }
            } else {      // B: transpose staging from [k][n] activations
                const int krow = tid >> 3;
                const float* Bk = Bp + (size_t)(kc * 32 + krow) * TT + n0;
                char* bb0 = basep + ABYTES + (sub * 2 + 0) * 16384;
                char* bb1 = basep + ABYTES + (sub * 2 + 1) * 16384;
                #pragma unroll
                for (int p = 0; p < 4; p++) {
                    const int nn = (tid & 7) * 4 + p * 32;
                    const float4 v0 = *(const float4*)&Bk[nn];
                    const float4 v1 = *(const float4*)&Bk[nn + 128];
                    *(float*)(bb0 + toff(nn + 0, krow, 16)) = v0.x;
                    *(float*)(bb0 + toff(nn + 1, krow, 16)) = v0.y;
                    *(float*)(bb0 + toff(nn + 2, krow, 16)) = v0.z;
                    *(float*)(bb0 + toff(nn + 3, krow, 16)) = v0.w;
                    *(float*)(bb1 + toff(nn + 0, krow, 16)) = v1.x;
                    *(float*)(bb1 + toff(nn + 1, krow, 16)) = v1.y;
                    *(float*)(bb1 + toff(nn + 2, krow, 16)) = v1.z;
                    *(float*)(bb1 + toff(nn + 3, krow, 16)) = v1.w;
                }
            }
        }
        __syncthreads();
        if (wid == 0 && elect_one()) {
            #pragma unroll
            for (int sub = 0; sub < KS; sub++) {
                const uint64_t bd0 = make_desc(base + ABYTES + (sub * 2 + 0) * 16384);
                const uint64_t bd1 = make_desc(base + ABYTES + (sub * 2 + 1) * 16384);
                #pragma unroll
                for (int j = 0; j < 4; j++) {
                    const bool acc = (i > 0) || (sub > 0) || (j > 0);
                    #pragma unroll
                    for (int mi = 0; mi < MT; mi++) {
                        const uint64_t ad = make_desc(base + (mi * KS + sub) * 16384);
                        mma_tf32_ss(tmem + (mi * 2 + 0) * 128, ad + j * 2, bd0 + j * 2, idesc, acc);
                        mma_tf32_ss(tmem + (mi * 2 + 1) * 128, ad + j * 2, bd1 + j * 2, idesc, acc);
                    }
                }
            }
            TC_COMMIT(mbar[bsel]);
        }
        __syncthreads();
    }
    mbar_wait(mbar[(nk - 1) & 1], (uint32_t)(((nk - 1) >> 1) & 1));
    TC_FENCE_AFTER();
    __syncthreads();

    // epilogue (R13-exact structure)
    const int wg = wid >> 2;
    const int sp = wid & 3;
    const uint32_t woff = (uint32_t)sp << 21;
    const int wg_tid = tid & 127;
    float* tsm = (float*)smb;
    const int wbase = wg * 32 * 133;

    #pragma unroll
    for (int mi = 0; mi < MT; mi++) {
        for (int h2 = 0; h2 < 2; h2++) {
            for (int it = 0; it < 2; it++) {
                const int c4 = it * 2 + wg;
                uint32_t regs[32];
                TC_LD_X32(regs, tmem + (mi * 2 + h2) * 128 + c4 * 32 + woff);
                TC_WAIT_LD();
                const int myrow = sp * 32 + lane;
                #pragma unroll
                for (int j = 0; j < 32; j++) tsm[wbase + j * 133 + myrow] = __uint_as_float(regs[j]);
                __syncthreads();
                const int n = wg_tid & 31;
                #pragma unroll
                for (int q = 0; q < 32; q++) {
                    const int m = (wg_tid >> 5) + q * 4;
                    float v = tsm[wbase + n * 133 + m] + bias[m0 + mi * 128 + m];
                    const size_t off = (size_t)(m0 + mi * 128 + m) * TT + n0 + h2 * 128 + c4 * 32 + n;
                    if (RESID) v += rp[off];
                    C[off] = v;
                }
                __syncthreads();
            }
        }
    }
    if (wid == 0) { TC_RELINQ(); TC_DEALLOC(tmem, MT * 256); }
#endif
}

// ---------------------------------------------------------------------------
// Single-pass flash attention (exact R11/R15-passing version)
// ---------------------------------------------------------------------------
__global__ void __launch_bounds__(256, 2) attn_tc(
    const float* __restrict__ qkv, float* __restrict__ a_out)
{
#if HAS_TCGEN05
    extern __shared__ char dsm_raw[];
    const uint32_t sraw = smem_u32(dsm_raw);
    const uint32_t sal = (sraw + 1023) & ~1023u;
    char* smb = dsm_raw + (sal - sraw);
    char* Kb = smb;
    char* Vb[2] = { smb + 32768, smb + 65536 };
    const uint32_t Kaddr = sal;
    const uint32_t Vaddr[2] = { sal + 32768, sal + 65536 };

    __shared__ uint32_t s_tmem;
    __shared__ __align__(8) uint64_t s_mbar[2];
    __shared__ float pmax[2][128], psum[2][128];
    __shared__ float m_s[128], l_s[128];

    const int tid = threadIdx.x;
    const int wid = tid >> 5;
    const int lane = tid & 31;
    const int sp = wid & 3;
    const int wg = wid >> 2;
    const uint32_t woff = (uint32_t)sp << 21;
    const int row = sp * 32 + lane;

    const int bh = blockIdx.y;
    const int b = bh >> 3, h = bh & 7;
    const int t0 = blockIdx.x * 128;

    const float* qp = qkv + ((size_t)(b * 3 * CC) + (size_t)h * 3 * CHH) * TT;
    const float* kp = qp + (size_t)CHH * TT;
    const float* vp = qp + (size_t)2 * CHH * TT;

    if (wid == 0) TC_ALLOC(smem_u32(&s_tmem), 256);
    if (tid == 0) { MBAR_INIT(smem_u32(&s_mbar[0]), 1); MBAR_INIT(smem_u32(&s_mbar[1]), 1); }
    if (wg == 0) { m_s[row] = -1e30f; l_s[row] = 0.f; }
    __syncthreads();
    uint32_t tmem;
    asm volatile("ld.shared.b32 %0, [%1];" : "=r"(tmem) : "r"(smem_u32(&s_tmem)));
    const uint32_t mb = smem_u32(&s_mbar[0]);
    const uint32_t mb2 = smem_u32(&s_mbar[1]);
    const uint32_t tS = tmem, tO = tmem + 128, tQ = tmem + 192;
    const uint32_t idS = IDESC(128, 128);
    const uint32_t idO = IDESC(128, 64);

    {
        uint32_t qreg[32];
        #pragma unroll
        for (int j = 0; j < 32; j++) {
            const int c = wg * 32 + j;
            qreg[j] = __float_as_uint(qp[(size_t)c * TT + t0 + row] * 0.125f);
        }
        TC_ST_X32(tQ + wg * 32 + woff, qreg);
        TC_WAIT_ST();
        TC_FENCE_BEFORE();
    }

    const uint64_t kdesc = make_desc(Kaddr);
    const uint64_t vdesc[2] = { make_desc(Vaddr[0]), make_desc(Vaddr[1]) };

    for (int st = 0; st < 8; st++) {
        const int s0 = st * 128;
        {
            const int c = tid >> 2;
            char* vb = Vb[st & 1];
            #pragma unroll
            for (int p = 0; p < 8; p++) {
                const int s = (tid & 3) * 4 + p * 16;
                const float4 v = *(const float4*)&kp[(size_t)c * TT + s0 + s];
                *(float*)(Kb + toff(s + 0, c, 16)) = v.x;
                *(float*)(Kb + toff(s + 1, c, 16)) = v.y;
                *(float*)(Kb + toff(s + 2, c, 16)) = v.z;
                *(float*)(Kb + toff(s + 3, c, 16)) = v.w;
                const float4 w = *(const float4*)&vp[(size_t)c * TT + s0 + s];
                *(float4*)(vb + toff(c, s, 8)) = w;
            }
        }
        __syncthreads();
        if (wid == 0 && elect_one()) {
            TC_FENCE_AFTER();
            if (st > 0) mbar_wait(mb2, (uint32_t)((st - 1) & 1));
            #pragma unroll
            for (int j = 0; j < 8; j++) {
                const uint64_t off = (uint64_t)((j & 3) * 2 + (j >> 2) * 1024);
                mma_tf32_ts(tS, tQ + j * 8, kdesc + off, idS, j > 0);
            }
            TC_COMMIT(mb);
        }
        mbar_wait(mb, (uint32_t)(st & 1));
        TC_FENCE_AFTER();

        uint32_t r0[32], r1[32];
        TC_LD_X32(r0, tS + wg * 64 + woff);
        TC_LD_X32(r1, tS + wg * 64 + 32 + woff);
        TC_WAIT_LD();
        float pm = -1e30f;
        #pragma unroll
        for (int j = 0; j < 32; j++) {
            pm = fmaxf(pm, __uint_as_float(r0[j]));
            pm = fmaxf(pm, __uint_as_float(r1[j]));
        }
        pmax[wg][row] = pm;
        __syncthreads();
        const float mold = m_s[row];
        const float mnew = fmaxf(mold, fmaxf(pmax[0][row], pmax[1][row]));
        const float alpha = __expf(mold - mnew);
        float psumv = 0.f;
        #pragma unroll
        for (int j = 0; j < 32; j++) {
            float v0 = __expf(__uint_as_float(r0[j]) - mnew);
            float v1 = __expf(__uint_as_float(r1[j]) - mnew);
            psumv += v0 + v1;
            r0[j] = __float_as_uint(v0);
            r1[j] = __float_as_uint(v1);
        }
        psum[wg][row] = psumv;
        TC_ST_X32(tS + wg * 64 + woff, r0);
        TC_ST_X32(tS + wg * 64 + 32 + woff, r1);
        if (st > 0) {
            uint32_t o[32];
            TC_LD_X32(o, tO + wg * 32 + woff);
            TC_WAIT_LD();
            #pragma unroll
            for (int j = 0; j < 32; j++)
                o[j] = __float_as_uint(__uint_as_float(o[j]) * alpha);
            TC_ST_X32(tO + wg * 32 + woff, o);
        }
        TC_WAIT_ST();
        TC_FENCE_BEFORE();
        __syncthreads();
        if (wg == 0) {
            l_s[row] = l_s[row] * alpha + psum[0][row] + psum[1][row];
            m_s[row] = mnew;
        }
        if (wid == 0 && elect_one()) {
            TC_FENCE_AFTER();
            #pragma unroll
            for (int j = 0; j < 16; j++) {
                const uint64_t off = (uint64_t)((j & 3) * 2 + (j >> 2) * 512);
                mma_tf32_ts(tO, tS + j * 8, vdesc[st & 1] + off, idO,
                            (st > 0) || (j > 0));
            }
            TC_COMMIT(mb2);
        }
    }

    mbar_wait(mb2, 1u);
    TC_FENCE_AFTER();
    __syncthreads();

    {
        uint32_t o[32];
        TC_LD_X32(o, tO + wg * 32 + woff);
        TC_WAIT_LD();
        const float inv = 1.f / l_s[row];
        float* ao = a_out + ((size_t)(b * CC) + (size_t)h * CHH) * TT + t0;
        #pragma unroll
        for (int j = 0; j < 32; j++)
            ao[(size_t)(wg * 32 + j) * TT + row] = __uint_as_float(o[j]) * inv;
    }
    __syncthreads();
    if (wid == 0) { TC_RELINQ(); TC_DEALLOC(tmem, 256); }
#endif
}

// ---------------------------------------------------------------------------
extern "C" void kernel_launch(void* const* d_in, const int* in_sizes, int n_in,
                              void* d_out, int out_size)
{
    const float* x      = (const float*)d_in[0];
    const float* norm_w = (const float*)d_in[1];
    const float* norm_b = (const float*)d_in[2];
    const float* qkv_w  = (const float*)d_in[3];
    const float* qkv_b  = (const float*)d_in[4];
    const float* proj_w = (const float*)d_in[5];
    const float* proj_b = (const float*)d_in[6];
    float* out = (float*)d_out;

    float *qkv_buf, *a_buf, *sc_buf, *sh_buf, *bx_buf, *wq_buf, *wp_buf;
    cudaGetSymbolAddress((void**)&qkv_buf, g_qkv);
    cudaGetSymbolAddress((void**)&a_buf, g_a);
    cudaGetSymbolAddress((void**)&sc_buf, g_scale);
    cudaGetSymbolAddress((void**)&sh_buf, g_shift);
    cudaGetSymbolAddress((void**)&bx_buf, g_bx);
    cudaGetSymbolAddress((void**)&wq_buf, g_wq);
    cudaGetSymbolAddress((void**)&wp_buf, g_wp);

    const int GEMM_QKV_SMEM = 132096;   // MT=2,KS=1: 128KB + pad
    const int GEMM_PRJ_SMEM = 197632;   // MT=1,KS=2: 192KB + pad
    const int ATTN_SMEM = 99328;
    cudaFuncSetAttribute((const void*)gemm_tc<false, 2, 1, true>,
                         cudaFuncAttributeMaxDynamicSharedMemorySize, GEMM_QKV_SMEM);
    cudaFuncSetAttribute((const void*)gemm_tc<true, 1, 2, false>,
                         cudaFuncAttributeMaxDynamicSharedMemorySize, GEMM_PRJ_SMEM);
    cudaFuncSetAttribute((const void*)attn_tc,
                         cudaFuncAttributeMaxDynamicSharedMemorySize, ATTN_SMEM);

    // 1. GN stats + weight/x-hat pre-swizzle
    gn_stats_kernel<<<BB * NG, 256>>>(x, norm_w, norm_b, sc_buf, sh_buf);
    wswz_kernel<<<dim3(16, 12), 128>>>(qkv_w, wq_buf, CC);
    wswz_kernel<<<dim3(16, 4), 128>>>(proj_w, wp_buf, CC);
    xhat_kernel<<<dim3(16, 8, BB), 128>>>(x, sc_buf, sh_buf, bx_buf);
    // 2. QKV GEMM: both operands pre-swizzled
    gemm_tc<false, 2, 1, true><<<dim3(TT / 256, 3 * CC / 256, BB), 256, GEMM_QKV_SMEM>>>(
        wq_buf, bx_buf, qkv_b, nullptr, qkv_buf, 3 * CC, CC);
    // 3. Attention
    attn_tc<<<dim3(TT / 128, BB * NHH), 256, ATTN_SMEM>>>(qkv_buf, a_buf);
    // 4. Proj: A pre-swizzled, B transposed in-kernel
    gemm_tc<true, 1, 2, false><<<dim3(TT / 256, CC / 128, BB), 256, GEMM_PRJ_SMEM>>>(
        wp_buf, a_buf, proj_b, x, out, CC, CC);
}